// round 14
// baseline (speedup 1.0000x reference)
#include <cuda_runtime.h>
#include <cuda_bf16.h>

#define NNODE 128
#define NM1   127            // edges per receiver
#define NRR   (NNODE * NM1)  // 16256 directed edges
#define BB    128
#define CC    16

// SW128-style smem swizzle on byte offsets: XOR bits [9:7] into [6:4].
// Conflict-free for both phase-1 writes (8 consecutive float4s per row) and
// phase-2 reads (stride-4 float4 column).
__device__ __forceinline__ unsigned swz(unsigned byte_off) {
    return byte_off ^ ((byte_off >> 3) & 0x70u);
}

// One CTA per (batch b, receiver r), 128 threads. R12 structure with the
// phase-1 loads explicitly FRONT-BATCHED (4 independent LDG.128 in flight
// per warp before any consumer) and occupancy relaxed to 12 CTAs/SM so the
// register file can hold all four loads live (defeats the 32-reg serialization
// that made R12 effectively MLP~1).
__global__ __launch_bounds__(128, 12) void attention2_denom_kernel(
    const float* __restrict__ x, float* __restrict__ out)
{
    const int r    = blockIdx.x;
    const int b    = blockIdx.y;
    const int t    = threadIdx.x;
    const int warp = t >> 5;
    const int lane = t & 31;

    __shared__ __align__(16) unsigned char v_s[NM1 * CC * 4 + 64]; // 8128B staged x
    __shared__ float4 ws4[4][4];     // per-warp exp sums: ws4[w][q] = ch 4q..4q+3
    __shared__ float4 rden4[4];      // reciprocal denominators, 16 channels

    const float4* __restrict__ src =
        reinterpret_cast<const float4*>(x + ((size_t)b * NRR + (size_t)r * NM1) * CC);

    // ---- Phase 1: front-batched coalesced streaming loads ------------------
    const bool p3 = (t < NM1 * 4 - 384);     // t < 124
    float4 g0 = __ldcs(src + t);
    float4 g1 = __ldcs(src + t + 128);
    float4 g2 = __ldcs(src + t + 256);
    float4 g3 = make_float4(0.f, 0.f, 0.f, 0.f);
    if (p3) g3 = __ldcs(src + t + 384);

    // exp + accumulate + stage (consumers in load order; all 4 loads already issued)
    float4 acc;
    acc.x = __expf(g0.x); acc.y = __expf(g0.y);
    acc.z = __expf(g0.z); acc.w = __expf(g0.w);
    *reinterpret_cast<float4*>(v_s + swz(16u * (unsigned)t)) = g0;

    acc.x += __expf(g1.x); acc.y += __expf(g1.y);
    acc.z += __expf(g1.z); acc.w += __expf(g1.w);
    *reinterpret_cast<float4*>(v_s + swz(16u * (unsigned)(t + 128))) = g1;

    acc.x += __expf(g2.x); acc.y += __expf(g2.y);
    acc.z += __expf(g2.z); acc.w += __expf(g2.w);
    *reinterpret_cast<float4*>(v_s + swz(16u * (unsigned)(t + 256))) = g2;

    if (p3) {
        acc.x += __expf(g3.x); acc.y += __expf(g3.y);
        acc.z += __expf(g3.z); acc.w += __expf(g3.w);
        *reinterpret_cast<float4*>(v_s + swz(16u * (unsigned)(t + 384))) = g3;
    }

    // ---- Reduce over edges: lanes with equal quad q = t&3 (masks 4,8,16) ---
    #pragma unroll
    for (int m = 4; m <= 16; m <<= 1) {
        acc.x += __shfl_xor_sync(0xffffffffu, acc.x, m);
        acc.y += __shfl_xor_sync(0xffffffffu, acc.y, m);
        acc.z += __shfl_xor_sync(0xffffffffu, acc.z, m);
        acc.w += __shfl_xor_sync(0xffffffffu, acc.w, m);
    }
    if (lane < 4) ws4[warp][lane] = acc;     // lane == its quad q
    __syncthreads();

    if (t < CC) {
        const float* wsf = reinterpret_cast<const float*>(ws4);
        float d = wsf[0 * CC + t] + wsf[1 * CC + t]
                + wsf[2 * CC + t] + wsf[3 * CC + t];
        reinterpret_cast<float*>(rden4)[t] = __frcp_rn(d);
    }
    __syncthreads();

    // ---- Phase 2: edge-owned readback + coalesced streaming stores ---------
    if (t < NM1) {
        float4 rd0 = rden4[0], rd1 = rden4[1], rd2 = rden4[2], rd3 = rden4[3];
        float4 v0 = *reinterpret_cast<const float4*>(v_s + swz(16u * (4u * t + 0)));
        float4 v1 = *reinterpret_cast<const float4*>(v_s + swz(16u * (4u * t + 1)));
        float4 v2 = *reinterpret_cast<const float4*>(v_s + swz(16u * (4u * t + 2)));
        float4 v3 = *reinterpret_cast<const float4*>(v_s + swz(16u * (4u * t + 3)));

        float* o = out + (size_t)b * CC * NRR + (size_t)r * NM1 + (size_t)t;
        __stcs(o +  0 * NRR, v0.x * rd0.x);  __stcs(o +  1 * NRR, v0.y * rd0.y);
        __stcs(o +  2 * NRR, v0.z * rd0.z);  __stcs(o +  3 * NRR, v0.w * rd0.w);
        __stcs(o +  4 * NRR, v1.x * rd1.x);  __stcs(o +  5 * NRR, v1.y * rd1.y);
        __stcs(o +  6 * NRR, v1.z * rd1.z);  __stcs(o +  7 * NRR, v1.w * rd1.w);
        __stcs(o +  8 * NRR, v2.x * rd2.x);  __stcs(o +  9 * NRR, v2.y * rd2.y);
        __stcs(o + 10 * NRR, v2.z * rd2.z);  __stcs(o + 11 * NRR, v2.w * rd2.w);
        __stcs(o + 12 * NRR, v3.x * rd3.x);  __stcs(o + 13 * NRR, v3.y * rd3.y);
        __stcs(o + 14 * NRR, v3.z * rd3.z);  __stcs(o + 15 * NRR, v3.w * rd3.w);
    }
}

extern "C" void kernel_launch(void* const* d_in, const int* in_sizes, int n_in,
                              void* d_out, int out_size)
{
    // d_in[0]: x  float32 [B, NR, C]
    // d_in[1]: receivers int32 [NR] — structurally i/(N-1), unused
    const float* x   = (const float*)d_in[0];
    float*       out = (float*)d_out;   // float32 [B, C, NR]

    dim3 grid(NNODE, BB);   // (receiver, batch)
    attention2_denom_kernel<<<grid, 128>>>(x, out);
}

// round 15
// speedup vs baseline: 1.0088x; 1.0088x over previous
#include <cuda_runtime.h>
#include <cuda_bf16.h>

#define NNODE 128
#define NM1   127            // edges per receiver
#define NRR   (NNODE * NM1)  // 16256 directed edges
#define BB    128
#define CC    16

// SW128-style smem swizzle on byte offsets: XOR bits [9:7] into [6:4].
// Conflict-free for both phase-1 writes (8 consecutive float4s per row) and
// phase-2 reads (stride-4 float4 column).
__device__ __forceinline__ unsigned swz(unsigned byte_off) {
    return byte_off ^ ((byte_off >> 3) & 0x70u);
}

// One CTA per (batch b, receiver r), 128 threads. R12 structure with the
// phase-1 loads explicitly FRONT-BATCHED (4 independent LDG.128 in flight
// per warp before any consumer) and occupancy relaxed to 12 CTAs/SM so the
// register file can hold all four loads live (defeats the 32-reg serialization
// that made R12 effectively MLP~1).
__global__ __launch_bounds__(128, 12) void attention2_denom_kernel(
    const float* __restrict__ x, float* __restrict__ out)
{
    const int r    = blockIdx.x;
    const int b    = blockIdx.y;
    const int t    = threadIdx.x;
    const int warp = t >> 5;
    const int lane = t & 31;

    __shared__ __align__(16) unsigned char v_s[NM1 * CC * 4 + 64]; // 8128B staged x
    __shared__ float4 ws4[4][4];     // per-warp exp sums: ws4[w][q] = ch 4q..4q+3
    __shared__ float4 rden4[4];      // reciprocal denominators, 16 channels

    const float4* __restrict__ src =
        reinterpret_cast<const float4*>(x + ((size_t)b * NRR + (size_t)r * NM1) * CC);

    // ---- Phase 1: front-batched coalesced streaming loads ------------------
    const bool p3 = (t < NM1 * 4 - 384);     // t < 124
    float4 g0 = __ldcs(src + t);
    float4 g1 = __ldcs(src + t + 128);
    float4 g2 = __ldcs(src + t + 256);
    float4 g3 = make_float4(0.f, 0.f, 0.f, 0.f);
    if (p3) g3 = __ldcs(src + t + 384);

    // exp + accumulate + stage (consumers in load order; all 4 loads already issued)
    float4 acc;
    acc.x = __expf(g0.x); acc.y = __expf(g0.y);
    acc.z = __expf(g0.z); acc.w = __expf(g0.w);
    *reinterpret_cast<float4*>(v_s + swz(16u * (unsigned)t)) = g0;

    acc.x += __expf(g1.x); acc.y += __expf(g1.y);
    acc.z += __expf(g1.z); acc.w += __expf(g1.w);
    *reinterpret_cast<float4*>(v_s + swz(16u * (unsigned)(t + 128))) = g1;

    acc.x += __expf(g2.x); acc.y += __expf(g2.y);
    acc.z += __expf(g2.z); acc.w += __expf(g2.w);
    *reinterpret_cast<float4*>(v_s + swz(16u * (unsigned)(t + 256))) = g2;

    if (p3) {
        acc.x += __expf(g3.x); acc.y += __expf(g3.y);
        acc.z += __expf(g3.z); acc.w += __expf(g3.w);
        *reinterpret_cast<float4*>(v_s + swz(16u * (unsigned)(t + 384))) = g3;
    }

    // ---- Reduce over edges: lanes with equal quad q = t&3 (masks 4,8,16) ---
    #pragma unroll
    for (int m = 4; m <= 16; m <<= 1) {
        acc.x += __shfl_xor_sync(0xffffffffu, acc.x, m);
        acc.y += __shfl_xor_sync(0xffffffffu, acc.y, m);
        acc.z += __shfl_xor_sync(0xffffffffu, acc.z, m);
        acc.w += __shfl_xor_sync(0xffffffffu, acc.w, m);
    }
    if (lane < 4) ws4[warp][lane] = acc;     // lane == its quad q
    __syncthreads();

    if (t < CC) {
        const float* wsf = reinterpret_cast<const float*>(ws4);
        float d = wsf[0 * CC + t] + wsf[1 * CC + t]
                + wsf[2 * CC + t] + wsf[3 * CC + t];
        reinterpret_cast<float*>(rden4)[t] = __frcp_rn(d);
    }
    __syncthreads();

    // ---- Phase 2: edge-owned readback + coalesced streaming stores ---------
    if (t < NM1) {
        float4 rd0 = rden4[0], rd1 = rden4[1], rd2 = rden4[2], rd3 = rden4[3];
        float4 v0 = *reinterpret_cast<const float4*>(v_s + swz(16u * (4u * t + 0)));
        float4 v1 = *reinterpret_cast<const float4*>(v_s + swz(16u * (4u * t + 1)));
        float4 v2 = *reinterpret_cast<const float4*>(v_s + swz(16u * (4u * t + 2)));
        float4 v3 = *reinterpret_cast<const float4*>(v_s + swz(16u * (4u * t + 3)));

        float* o = out + (size_t)b * CC * NRR + (size_t)r * NM1 + (size_t)t;
        __stcs(o +  0 * NRR, v0.x * rd0.x);  __stcs(o +  1 * NRR, v0.y * rd0.y);
        __stcs(o +  2 * NRR, v0.z * rd0.z);  __stcs(o +  3 * NRR, v0.w * rd0.w);
        __stcs(o +  4 * NRR, v1.x * rd1.x);  __stcs(o +  5 * NRR, v1.y * rd1.y);
        __stcs(o +  6 * NRR, v1.z * rd1.z);  __stcs(o +  7 * NRR, v1.w * rd1.w);
        __stcs(o +  8 * NRR, v2.x * rd2.x);  __stcs(o +  9 * NRR, v2.y * rd2.y);
        __stcs(o + 10 * NRR, v2.z * rd2.z);  __stcs(o + 11 * NRR, v2.w * rd2.w);
        __stcs(o + 12 * NRR, v3.x * rd3.x);  __stcs(o + 13 * NRR, v3.y * rd3.y);
        __stcs(o + 14 * NRR, v3.z * rd3.z);  __stcs(o + 15 * NRR, v3.w * rd3.w);
    }
}

extern "C" void kernel_launch(void* const* d_in, const int* in_sizes, int n_in,
                              void* d_out, int out_size)
{
    // d_in[0]: x  float32 [B, NR, C]
    // d_in[1]: receivers int32 [NR] — structurally i/(N-1), unused
    const float* x   = (const float*)d_in[0];
    float*       out = (float*)d_out;   // float32 [B, C, NR]

    dim3 grid(NNODE, BB);   // (receiver, batch)
    attention2_denom_kernel<<<grid, 128>>>(x, out);
}